// round 1
// baseline (speedup 1.0000x reference)
#include <cuda_runtime.h>

#define NH     16
#define DMODEL 1024
#define HDIM   64
#define NEMB   40001
#define NB     2
#define SEQ    512

// ---------------- device scratch (static, allowed) ----------------
__device__ float g_Tx[NEMB * NH];                       // projected x_table  (2.56 MB)
__device__ float g_Ty[NEMB * NH];                       // projected y_table
__device__ float g_Qp[NB * NH * SEQ * HDIM];            // Q projected [b][h][q][d]
__device__ float g_Kp[NB * NH * SEQ * HDIM];            // K projected [b][h][k][d]
__device__ float g_Vp[NB * NH * SEQ * HDIM];            // V projected [b][h][k][d]
__device__ float g_bias[(size_t)NB * NH * SEQ * SEQ];   // bias [b][h][q][k]  (33.5 MB)
__device__ float g_att[NB * SEQ * DMODEL];              // attn out [b][q][h*64+d]

// ---------------- kernel 1: project embedding tables through Wb ----------------
// Tx[r][h] = sum_d x_table[r, h*16+d] * Wb[d]
__global__ __launch_bounds__(256) void k_project(const float* __restrict__ xt,
                                                 const float* __restrict__ yt,
                                                 const float* __restrict__ Wb) {
    int id = blockIdx.x * 256 + threadIdx.x;
    if (id >= 2 * NEMB * NH) return;
    int which = (id >= NEMB * NH);
    int rid = which ? id - NEMB * NH : id;
    int r = rid >> 4, h = rid & 15;
    const float4* row = (const float4*)((which ? yt : xt) + (size_t)r * 256 + h * 16);
    const float4* wb = (const float4*)Wb;
    float s = 0.f;
#pragma unroll
    for (int q = 0; q < 4; q++) {
        float4 v = row[q], w = wb[q];
        s += v.x * w.x + v.y * w.y + v.z * w.z + v.w * w.w;
    }
    (which ? g_Ty : g_Tx)[rid] = s;
}

// ---------------- kernel 2: positional bias ----------------
// bias[b][h][i][j] = sigmoid(Tx[idx(qx[j]-kx[i])][h] + Ty[idx(qy[j]-ky[i])][h] + bb)
// NOTE the reference's transpose: bias at (q-row i, k-col j) uses qx at j, kx at i.
__global__ __launch_bounds__(256) void k_bias(const float* __restrict__ qx,
                                              const float* __restrict__ qy,
                                              const float* __restrict__ kx,
                                              const float* __restrict__ ky,
                                              const float* __restrict__ bbp) {
    __shared__ float sm[16 * 256];
    int b = blockIdx.z;
    int i0 = blockIdx.y * 16, j0 = blockIdx.x * 16;
    int t = threadIdx.x;
    int i = i0 + (t >> 4), j = j0 + (t & 15);
    float bb = bbp[0];
    float dx = qx[b * SEQ + j] - kx[b * SEQ + i];
    float dy = qy[b * SEQ + j] - ky[b * SEQ + i];
    dx = fminf(fmaxf(dx, -1000.f), 1000.f);
    dy = fminf(fmaxf(dy, -1000.f), 1000.f);
    int ix = (int)rintf((dx + 1000.f) * 20.f);   // rintf = round-half-even (matches jnp.round)
    int iy = (int)rintf((dy + 1000.f) * 20.f);
    const float4* px = (const float4*)(g_Tx + (size_t)ix * 16);
    const float4* py = (const float4*)(g_Ty + (size_t)iy * 16);
#pragma unroll
    for (int q = 0; q < 4; q++) {
        float4 a = px[q], c = py[q];
        float v0 = a.x + c.x + bb;
        float v1 = a.y + c.y + bb;
        float v2 = a.z + c.z + bb;
        float v3 = a.w + c.w + bb;
        sm[(q * 4 + 0) * 256 + t] = 1.f / (1.f + __expf(-v0));
        sm[(q * 4 + 1) * 256 + t] = 1.f / (1.f + __expf(-v1));
        sm[(q * 4 + 2) * 256 + t] = 1.f / (1.f + __expf(-v2));
        sm[(q * 4 + 3) * 256 + t] = 1.f / (1.f + __expf(-v3));
    }
    __syncthreads();
    int h = t >> 4, w = t & 15;
#pragma unroll
    for (int ii = 0; ii < 16; ii++) {
        g_bias[(((size_t)(b * NH + h)) * SEQ + (i0 + ii)) * SEQ + (j0 + w)] =
            sm[h * 256 + ii * 16 + w];
    }
}

// ---------------- SGEMM body: C = A(1024xM rows) @ W(1024x1024) + bias ----------------
// BM=BN=64, BK=8, 64 threads, 8x8 microtile.
// MODE 0: scatter into [b][h][n][d] layout.  MODE 1: plain row-major.
template <int MODE>
__device__ __forceinline__ void gemm_body(const float* __restrict__ A,
                                          const float* __restrict__ W,
                                          const float* __restrict__ bias,
                                          float* __restrict__ C) {
    __shared__ float As[8][64];   // [k][m] transposed
    __shared__ float Bs[8][64];   // [k][n]
    int t = threadIdx.x;
    int m0 = blockIdx.y * 64, n0 = blockIdx.x * 64;
    int tx = t & 7, ty = t >> 3;
    float acc[8][8];
#pragma unroll
    for (int i = 0; i < 8; i++)
#pragma unroll
        for (int j = 0; j < 8; j++) acc[i][j] = 0.f;

    const float* Arow = A + (size_t)(m0 + t) * DMODEL;
    int kk = t >> 3, c4 = (t & 7) * 4;

    for (int k0 = 0; k0 < DMODEL; k0 += 8) {
        float4 a0 = *(const float4*)(Arow + k0);
        float4 a1 = *(const float4*)(Arow + k0 + 4);
        As[0][t] = a0.x; As[1][t] = a0.y; As[2][t] = a0.z; As[3][t] = a0.w;
        As[4][t] = a1.x; As[5][t] = a1.y; As[6][t] = a1.z; As[7][t] = a1.w;
        *(float4*)&Bs[kk][c4]      = *(const float4*)(W + (size_t)(k0 + kk) * DMODEL + n0 + c4);
        *(float4*)&Bs[kk][c4 + 32] = *(const float4*)(W + (size_t)(k0 + kk) * DMODEL + n0 + c4 + 32);
        __syncthreads();
#pragma unroll
        for (int k = 0; k < 8; k++) {
            float4 aA = *(float4*)&As[k][ty * 8];
            float4 aB = *(float4*)&As[k][ty * 8 + 4];
            float4 bA = *(float4*)&Bs[k][tx * 8];
            float4 bB = *(float4*)&Bs[k][tx * 8 + 4];
            float av[8] = {aA.x, aA.y, aA.z, aA.w, aB.x, aB.y, aB.z, aB.w};
            float bw[8] = {bA.x, bA.y, bA.z, bA.w, bB.x, bB.y, bB.z, bB.w};
#pragma unroll
            for (int i = 0; i < 8; i++)
#pragma unroll
                for (int j = 0; j < 8; j++) acc[i][j] += av[i] * bw[j];
        }
        __syncthreads();
    }

    float bcol[8];
#pragma unroll
    for (int j = 0; j < 8; j++) bcol[j] = bias[n0 + tx * 8 + j];
#pragma unroll
    for (int i = 0; i < 8; i++) {
        int r = m0 + ty * 8 + i;
#pragma unroll
        for (int jq = 0; jq < 2; jq++) {
            int c = n0 + tx * 8 + jq * 4;
            float4 v;
            v.x = acc[i][jq * 4 + 0] + bcol[jq * 4 + 0];
            v.y = acc[i][jq * 4 + 1] + bcol[jq * 4 + 1];
            v.z = acc[i][jq * 4 + 2] + bcol[jq * 4 + 2];
            v.w = acc[i][jq * 4 + 3] + bcol[jq * 4 + 3];
            size_t idx;
            if (MODE == 0) {
                int bb_ = r >> 9, n = r & 511;
                int hh = c >> 6, d = c & 63;
                idx = (((size_t)(bb_ * NH + hh)) * SEQ + n) * HDIM + d;
            } else {
                idx = (size_t)r * DMODEL + c;
            }
            *(float4*)(C + idx) = v;
        }
    }
}

__global__ __launch_bounds__(64) void k_gemm_qkv(
    const float* __restrict__ Aq, const float* __restrict__ Ak, const float* __restrict__ Av,
    const float* __restrict__ Wq, const float* __restrict__ Wk, const float* __restrict__ Wv,
    const float* __restrict__ bq, const float* __restrict__ bk, const float* __restrict__ bv) {
    int z = blockIdx.z;
    const float* A = (z == 0) ? Aq : (z == 1) ? Ak : Av;
    const float* W = (z == 0) ? Wq : (z == 1) ? Wk : Wv;
    const float* bi = (z == 0) ? bq : (z == 1) ? bk : bv;
    float* C = (z == 0) ? g_Qp : (z == 1) ? g_Kp : g_Vp;
    gemm_body<0>(A, W, bi, C);
}

__global__ __launch_bounds__(64) void k_gemm_out(const float* __restrict__ Wo,
                                                 const float* __restrict__ bo,
                                                 float* __restrict__ out) {
    gemm_body<1>(g_att, Wo, bo, out);
}

// ---------------- kernel 4: fused attention (flash-style, one (b,h,q-tile) per block) ----------------
__global__ __launch_bounds__(256) void k_attn() {
    __shared__ float Qs[64][64];   // [d][i]  (Q transposed)
    __shared__ float KP[64][64];   // K as [d][j], then reused for P as [i][j]
    __shared__ float Vs[64][64];   // [k][d]
    int b = blockIdx.z, h = blockIdx.y, q0 = blockIdx.x * 64;
    int t = threadIdx.x, tx = t & 15, ty = t >> 4;
    const float* Qg = g_Qp + (size_t)(b * NH + h) * SEQ * HDIM;
    const float* Kg = g_Kp + (size_t)(b * NH + h) * SEQ * HDIM;
    const float* Vg = g_Vp + (size_t)(b * NH + h) * SEQ * HDIM;
    const float* Bg = g_bias + ((size_t)(b * NH + h) * SEQ + q0) * SEQ;

    // load Q transposed: lane->row mapping keeps the smem transpose stores conflict-free
#pragma unroll
    for (int u = 0; u < 4; u++) {
        int f = t + u * 256;
        int r = f & 63, cq = f >> 6;
        float4 v = *(const float4*)(Qg + (size_t)(q0 + r) * HDIM + cq * 4);
        Qs[cq * 4 + 0][r] = v.x; Qs[cq * 4 + 1][r] = v.y;
        Qs[cq * 4 + 2][r] = v.z; Qs[cq * 4 + 3][r] = v.w;
    }

    float m_[4], l_[4], acc[4][4];
#pragma unroll
    for (int i = 0; i < 4; i++) {
        m_[i] = -1e30f; l_[i] = 0.f;
#pragma unroll
        for (int j = 0; j < 4; j++) acc[i][j] = 0.f;
    }

    for (int k0 = 0; k0 < SEQ; k0 += 64) {
        __syncthreads();   // prev-iter PV reads / initial Q-load done before overwriting tiles
#pragma unroll
        for (int u = 0; u < 4; u++) {
            int f = t + u * 256;
            int r = f & 63, cq = f >> 6;
            float4 kv = *(const float4*)(Kg + (size_t)(k0 + r) * HDIM + cq * 4);
            KP[cq * 4 + 0][r] = kv.x; KP[cq * 4 + 1][r] = kv.y;
            KP[cq * 4 + 2][r] = kv.z; KP[cq * 4 + 3][r] = kv.w;
            int rv = f >> 4, cv = (f & 15) * 4;
            float4 vv = *(const float4*)(Vg + (size_t)(k0 + rv) * HDIM + cv);
            *(float4*)&Vs[rv][cv] = vv;
        }
        __syncthreads();

        // S = Q K^T for this 64x64 tile; thread owns 4x4 frag
        float s[4][4];
#pragma unroll
        for (int i = 0; i < 4; i++)
#pragma unroll
            for (int j = 0; j < 4; j++) s[i][j] = 0.f;
#pragma unroll 8
        for (int d = 0; d < 64; d++) {
            float4 qf = *(float4*)&Qs[d][ty * 4];
            float4 kf = *(float4*)&KP[d][tx * 4];
            float qa[4] = {qf.x, qf.y, qf.z, qf.w};
            float ka[4] = {kf.x, kf.y, kf.z, kf.w};
#pragma unroll
            for (int i = 0; i < 4; i++)
#pragma unroll
                for (int j = 0; j < 4; j++) s[i][j] += qa[i] * ka[j];
        }

        // scale + bias + online softmax (row groups = 16 lanes sharing ty)
#pragma unroll
        for (int ii = 0; ii < 4; ii++) {
            float4 bf = *(const float4*)(Bg + (size_t)(ty * 4 + ii) * SEQ + k0 + tx * 4);
            s[ii][0] = s[ii][0] * 0.125f + bf.x;
            s[ii][1] = s[ii][1] * 0.125f + bf.y;
            s[ii][2] = s[ii][2] * 0.125f + bf.z;
            s[ii][3] = s[ii][3] * 0.125f + bf.w;
            float mx = fmaxf(fmaxf(s[ii][0], s[ii][1]), fmaxf(s[ii][2], s[ii][3]));
#pragma unroll
            for (int o = 1; o < 16; o <<= 1) mx = fmaxf(mx, __shfl_xor_sync(0xffffffffu, mx, o));
            float mn = fmaxf(m_[ii], mx);
            float corr = __expf(m_[ii] - mn);
            float rs = 0.f;
#pragma unroll
            for (int j = 0; j < 4; j++) {
                float p = __expf(s[ii][j] - mn);
                s[ii][j] = p; rs += p;
            }
#pragma unroll
            for (int o = 1; o < 16; o <<= 1) rs += __shfl_xor_sync(0xffffffffu, rs, o);
            l_[ii] = l_[ii] * corr + rs;
            m_[ii] = mn;
#pragma unroll
            for (int j = 0; j < 4; j++) acc[ii][j] *= corr;
        }

        __syncthreads();   // all S reads of KP (K data) done
        // store P row-major [i][j] into KP
#pragma unroll
        for (int ii = 0; ii < 4; ii++)
            *(float4*)&KP[ty * 4 + ii][tx * 4] =
                make_float4(s[ii][0], s[ii][1], s[ii][2], s[ii][3]);
        __syncthreads();

        // O += P @ V ; P reads are lane-broadcast (free), V reads float4
#pragma unroll 8
        for (int k = 0; k < 64; k++) {
            float4 vf = *(float4*)&Vs[k][tx * 4];
            float va[4] = {vf.x, vf.y, vf.z, vf.w};
#pragma unroll
            for (int ii = 0; ii < 4; ii++) {
                float p = KP[ty * 4 + ii][k];
                acc[ii][0] += p * va[0]; acc[ii][1] += p * va[1];
                acc[ii][2] += p * va[2]; acc[ii][3] += p * va[3];
            }
        }
    }

#pragma unroll
    for (int ii = 0; ii < 4; ii++) {
        float rl = 1.f / l_[ii];
        int q = q0 + ty * 4 + ii;
        float4 o = make_float4(acc[ii][0] * rl, acc[ii][1] * rl,
                               acc[ii][2] * rl, acc[ii][3] * rl);
        // write in [b][q][h][d] = row-major (1024 x 1024) for the output GEMM
        *(float4*)(g_att + ((size_t)(b * SEQ + q) * NH + h) * HDIM + tx * 4) = o;
    }
}

// ---------------- launch ----------------
extern "C" void kernel_launch(void* const* d_in, const int* in_sizes, int n_in,
                              void* d_out, int out_size) {
    (void)in_sizes; (void)n_in; (void)out_size;
    const float* query = (const float*)d_in[0];
    const float* key   = (const float*)d_in[1];
    const float* value = (const float*)d_in[2];
    const float* qx    = (const float*)d_in[3];
    const float* qy    = (const float*)d_in[4];
    const float* kx    = (const float*)d_in[5];
    const float* ky    = (const float*)d_in[6];
    const float* Wq    = (const float*)d_in[7];
    const float* bq    = (const float*)d_in[8];
    const float* Wk    = (const float*)d_in[9];
    const float* bk    = (const float*)d_in[10];
    const float* Wv    = (const float*)d_in[11];
    const float* bv    = (const float*)d_in[12];
    const float* Wo    = (const float*)d_in[13];
    const float* bo    = (const float*)d_in[14];
    const float* xt    = (const float*)d_in[15];
    const float* yt    = (const float*)d_in[16];
    const float* Wb    = (const float*)d_in[17];
    const float* bb    = (const float*)d_in[18];
    float* out = (float*)d_out;

    k_project<<<(2 * NEMB * NH + 255) / 256, 256>>>(xt, yt, Wb);
    k_bias<<<dim3(SEQ / 16, SEQ / 16, NB), 256>>>(qx, qy, kx, ky, bb);
    k_gemm_qkv<<<dim3(DMODEL / 64, (NB * SEQ) / 64, 3), 64>>>(query, key, value,
                                                              Wq, Wk, Wv, bq, bk, bv);
    k_attn<<<dim3(SEQ / 64, NH, NB), 256>>>();
    k_gemm_out<<<dim3(DMODEL / 64, (NB * SEQ) / 64), 64>>>(Wo, bo, out);
}

// round 3
// speedup vs baseline: 1.6137x; 1.6137x over previous
#include <cuda_runtime.h>
#include <cuda_bf16.h>
#include <cstdint>

#define NH     16
#define DMODEL 1024
#define HDIM   64
#define NEMB   40001
#define NB     2
#define SEQ    512

// ---------------- device scratch ----------------
__device__ float g_Tx[NEMB * NH];
__device__ float g_Ty[NEMB * NH];
__device__ float g_Qp[NB * NH * SEQ * HDIM];
__device__ float g_Kp[NB * NH * SEQ * HDIM];
__device__ float g_Vp[NB * NH * SEQ * HDIM];
__device__ float g_bias[(size_t)NB * NH * SEQ * SEQ];
__device__ float g_att[NB * SEQ * DMODEL];

// bf16 hi/lo split operands
__device__ __nv_bfloat16 g_actH[3 * DMODEL * DMODEL];   // q,k,v activations [m][k]
__device__ __nv_bfloat16 g_actL[3 * DMODEL * DMODEL];
__device__ __nv_bfloat16 g_WtH[4 * DMODEL * DMODEL];    // Wq,Wk,Wv,Wo transposed [n][k]
__device__ __nv_bfloat16 g_WtL[4 * DMODEL * DMODEL];
__device__ __nv_bfloat16 g_attH[DMODEL * DMODEL];
__device__ __nv_bfloat16 g_attL[DMODEL * DMODEL];

// ---------------- non-gated PTX helpers ----------------
__device__ __forceinline__ uint32_t smem_u32(const void* p) {
    uint32_t a;
    asm("{ .reg .u64 t; cvta.to.shared.u64 t, %1; cvt.u32.u64 %0, t; }" : "=r"(a) : "l"(p));
    return a;
}
__device__ __forceinline__ void cp_async16(uint32_t saddr, const void* gptr) {
    asm volatile("cp.async.cg.shared.global [%0], [%1], 16;" :: "r"(saddr), "l"(gptr) : "memory");
}
#define CP_COMMIT() asm volatile("cp.async.commit_group;" ::: "memory")
#define CP_WAIT(n)  asm volatile("cp.async.wait_group %0;" :: "n"(n) : "memory")

__device__ __forceinline__ void ldsm_x4(uint32_t* r, uint32_t addr) {
    asm volatile("ldmatrix.sync.aligned.m8n8.x4.shared.b16 {%0,%1,%2,%3}, [%4];"
                 : "=r"(r[0]), "=r"(r[1]), "=r"(r[2]), "=r"(r[3]) : "r"(addr));
}
__device__ __forceinline__ void ldsm_x2(uint32_t* r, uint32_t addr) {
    asm volatile("ldmatrix.sync.aligned.m8n8.x2.shared.b16 {%0,%1}, [%2];"
                 : "=r"(r[0]), "=r"(r[1]) : "r"(addr));
}
__device__ __forceinline__ void mma16816(float* d, const uint32_t* a, const uint32_t* b) {
    asm volatile("mma.sync.aligned.m16n8k16.row.col.f32.bf16.bf16.f32 "
                 "{%0,%1,%2,%3}, {%4,%5,%6,%7}, {%8,%9}, {%0,%1,%2,%3};"
                 : "+f"(d[0]), "+f"(d[1]), "+f"(d[2]), "+f"(d[3])
                 : "r"(a[0]), "r"(a[1]), "r"(a[2]), "r"(a[3]), "r"(b[0]), "r"(b[1]));
}

// ---------------- kernel 1: project embedding tables through Wb ----------------
__global__ __launch_bounds__(256) void k_project(const float* __restrict__ xt,
                                                 const float* __restrict__ yt,
                                                 const float* __restrict__ Wb) {
    int id = blockIdx.x * 256 + threadIdx.x;
    if (id >= 2 * NEMB * NH) return;
    int which = (id >= NEMB * NH);
    int rid = which ? id - NEMB * NH : id;
    int r = rid >> 4, h = rid & 15;
    const float4* row = (const float4*)((which ? yt : xt) + (size_t)r * 256 + h * 16);
    const float4* wb = (const float4*)Wb;
    float s = 0.f;
#pragma unroll
    for (int q = 0; q < 4; q++) {
        float4 v = row[q], w = wb[q];
        s += v.x * w.x + v.y * w.y + v.z * w.z + v.w * w.w;
    }
    (which ? g_Ty : g_Tx)[rid] = s;
}

// ---------------- kernel 2: positional bias ----------------
__global__ __launch_bounds__(256) void k_bias(const float* __restrict__ qx,
                                              const float* __restrict__ qy,
                                              const float* __restrict__ kx,
                                              const float* __restrict__ ky,
                                              const float* __restrict__ bbp) {
    __shared__ float sm[16 * 256];
    int b = blockIdx.z;
    int i0 = blockIdx.y * 16, j0 = blockIdx.x * 16;
    int t = threadIdx.x;
    int i = i0 + (t >> 4), j = j0 + (t & 15);
    float bb = bbp[0];
    float dx = qx[b * SEQ + j] - kx[b * SEQ + i];
    float dy = qy[b * SEQ + j] - ky[b * SEQ + i];
    dx = fminf(fmaxf(dx, -1000.f), 1000.f);
    dy = fminf(fmaxf(dy, -1000.f), 1000.f);
    int ix = (int)rintf((dx + 1000.f) * 20.f);
    int iy = (int)rintf((dy + 1000.f) * 20.f);
    const float4* px = (const float4*)(g_Tx + (size_t)ix * 16);
    const float4* py = (const float4*)(g_Ty + (size_t)iy * 16);
#pragma unroll
    for (int q = 0; q < 4; q++) {
        float4 a = px[q], c = py[q];
        float v0 = a.x + c.x + bb, v1 = a.y + c.y + bb;
        float v2 = a.z + c.z + bb, v3 = a.w + c.w + bb;
        sm[(q * 4 + 0) * 256 + t] = 1.f / (1.f + __expf(-v0));
        sm[(q * 4 + 1) * 256 + t] = 1.f / (1.f + __expf(-v1));
        sm[(q * 4 + 2) * 256 + t] = 1.f / (1.f + __expf(-v2));
        sm[(q * 4 + 3) * 256 + t] = 1.f / (1.f + __expf(-v3));
    }
    __syncthreads();
    int h = t >> 4, w = t & 15;
#pragma unroll
    for (int ii = 0; ii < 16; ii++) {
        g_bias[(((size_t)(b * NH + h)) * SEQ + (i0 + ii)) * SEQ + (j0 + w)] =
            sm[h * 256 + ii * 16 + w];
    }
}

// ---------------- bf16 hi/lo split helpers ----------------
__device__ __forceinline__ void split4(float4 x, __nv_bfloat162* ph, __nv_bfloat162* pl) {
    __nv_bfloat162 h01 = __floats2bfloat162_rn(x.x, x.y);
    __nv_bfloat162 h23 = __floats2bfloat162_rn(x.z, x.w);
    __nv_bfloat162 l01 = __floats2bfloat162_rn(x.x - __bfloat162float(__low2bfloat16(h01)),
                                               x.y - __bfloat162float(__high2bfloat16(h01)));
    __nv_bfloat162 l23 = __floats2bfloat162_rn(x.z - __bfloat162float(__low2bfloat16(h23)),
                                               x.w - __bfloat162float(__high2bfloat16(h23)));
    ph[0] = h01; ph[1] = h23; pl[0] = l01; pl[1] = l23;
}

__global__ __launch_bounds__(256) void k_convA(const float* __restrict__ q,
                                               const float* __restrict__ k,
                                               const float* __restrict__ v) {
    int z = blockIdx.z;
    const float* src = (z == 0) ? q : (z == 1) ? k : v;
    __nv_bfloat16* H = g_actH + (size_t)z * DMODEL * DMODEL;
    __nv_bfloat16* L = g_actL + (size_t)z * DMODEL * DMODEL;
    int i = blockIdx.x * 256 + threadIdx.x;
    float4 x = ((const float4*)src)[i];
    split4(x, (__nv_bfloat162*)(H + (size_t)i * 4), (__nv_bfloat162*)(L + (size_t)i * 4));
}

__global__ void k_convW(const float* __restrict__ Wq, const float* __restrict__ Wk,
                        const float* __restrict__ Wv, const float* __restrict__ Wo) {
    __shared__ float t[32][33];
    int z = blockIdx.z;
    const float* W = (z == 0) ? Wq : (z == 1) ? Wk : (z == 2) ? Wv : Wo;
    __nv_bfloat16* H = g_WtH + (size_t)z * DMODEL * DMODEL;
    __nv_bfloat16* L = g_WtL + (size_t)z * DMODEL * DMODEL;
    int nb = blockIdx.x * 32, kb = blockIdx.y * 32;
    int tx = threadIdx.x, ty = threadIdx.y;  // 32 x 8
#pragma unroll
    for (int i = 0; i < 4; i++)
        t[ty + i * 8][tx] = W[(size_t)(kb + ty + i * 8) * DMODEL + nb + tx];
    __syncthreads();
#pragma unroll
    for (int i = 0; i < 4; i++) {
        int n = nb + ty + i * 8, k = kb + tx;
        float v = t[tx][ty + i * 8];
        __nv_bfloat16 h = __float2bfloat16(v);
        H[(size_t)n * DMODEL + k] = h;
        L[(size_t)n * DMODEL + k] = __float2bfloat16(v - __bfloat162float(h));
    }
}

__global__ __launch_bounds__(256) void k_convAtt() {
    int i = blockIdx.x * 256 + threadIdx.x;
    float4 x = ((const float4*)g_att)[i];
    split4(x, (__nv_bfloat162*)(g_attH + (size_t)i * 4), (__nv_bfloat162*)(g_attL + (size_t)i * 4));
}

// ---------------- warp-mma GEMM: C = A @ Wt^T + bias ----------------
// 3-term hi/lo split folded into one K=3072 GEMM:
//   phase 0: Ah*Bh   phase 1: Al*Bh   phase 2: Ah*Bl
// BM=BN=128, BK=32, 8 warps (2m x 4n), warp tile 64x32, double-buffered cp.async.
// Smem tile row = 32 bf16 = 64B = 4 chunks of 16B; swizzle: chunk ^= (row>>1)&3.
#define NKITER 96

template <int MODE>
__device__ __forceinline__ void mma_body(const __nv_bfloat16* __restrict__ Ah,
                                         const __nv_bfloat16* __restrict__ Al,
                                         const __nv_bfloat16* __restrict__ Bh,
                                         const __nv_bfloat16* __restrict__ Bl,
                                         const float* __restrict__ bias,
                                         float* __restrict__ C) {
    __shared__ __align__(1024) char smem[2][16384];   // per stage: A 8KB | B 8KB
    int tid = threadIdx.x, lane = tid & 31, wid = tid >> 5;
    int wm = wid & 1, wn = wid >> 1;                  // 2 x 4 warp grid
    int m0 = blockIdx.y * 128, n0 = blockIdx.x * 128;
    uint32_t sbase = smem_u32(smem);

    float acc[4][4][4];
#pragma unroll
    for (int i = 0; i < 4; i++)
#pragma unroll
        for (int j = 0; j < 4; j++)
#pragma unroll
            for (int r = 0; r < 4; r++) acc[i][j][r] = 0.f;

    auto issue_tile = [&](int ki, int s) {
        int phase = ki >> 5;
        int kk = (ki & 31) * 32;
        const __nv_bfloat16* Ap = (phase == 1) ? Al : Ah;
        const __nv_bfloat16* Bp = (phase == 2) ? Bl : Bh;
        uint32_t sA = sbase + s * 16384, sB = sA + 8192;
#pragma unroll
        for (int j = 0; j < 2; j++) {
            int idx = tid + j * 256;                   // 512 chunks
            int row = idx >> 2, c = idx & 3;
            int cs = c ^ ((row >> 1) & 3);
            cp_async16(sA + row * 64 + cs * 16, Ap + (size_t)(m0 + row) * DMODEL + kk + c * 8);
            cp_async16(sB + row * 64 + cs * 16, Bp + (size_t)(n0 + row) * DMODEL + kk + c * 8);
        }
        CP_COMMIT();
    };

    issue_tile(0, 0);
    for (int ki = 0; ki < NKITER; ki++) {
        int s = ki & 1;
        if (ki + 1 < NKITER) {
            issue_tile(ki + 1, s ^ 1);
            CP_WAIT(1);
        } else {
            CP_WAIT(0);
        }
        __syncthreads();
        uint32_t sA = sbase + s * 16384, sB = sA + 8192;
#pragma unroll
        for (int kq = 0; kq < 2; kq++) {
            uint32_t af[4][4], bf[4][2];
#pragma unroll
            for (int im = 0; im < 4; im++) {
                int row = wm * 64 + im * 16 + (lane & 15);
                int c = kq * 2 + (lane >> 4);
                int cs = c ^ ((row >> 1) & 3);
                ldsm_x4(af[im], sA + row * 64 + cs * 16);
            }
#pragma unroll
            for (int jn = 0; jn < 4; jn++) {
                int row = wn * 32 + jn * 8 + (lane & 7);
                int c = kq * 2 + ((lane >> 3) & 1);
                int cs = c ^ ((row >> 1) & 3);
                ldsm_x2(bf[jn], sB + row * 64 + cs * 16);
            }
#pragma unroll
            for (int im = 0; im < 4; im++)
#pragma unroll
                for (int jn = 0; jn < 4; jn++) mma16816(acc[im][jn], af[im], bf[jn]);
        }
        __syncthreads();
    }

    // epilogue: add bias, store (MODE 0: head-scatter; MODE 1: row-major)
#pragma unroll
    for (int im = 0; im < 4; im++) {
#pragma unroll
        for (int jn = 0; jn < 4; jn++) {
            int col = n0 + wn * 32 + jn * 8 + 2 * (lane & 3);
            float b0 = bias[col], b1 = bias[col + 1];
#pragma unroll
            for (int half = 0; half < 2; half++) {
                int m = m0 + wm * 64 + im * 16 + (lane >> 2) + half * 8;
                size_t idx;
                if (MODE == 0) {
                    int bidx = m >> 9, nseq = m & 511;
                    int h = col >> 6, d = col & 63;
                    idx = (((size_t)(bidx * NH + h)) * SEQ + nseq) * HDIM + d;
                } else {
                    idx = (size_t)m * DMODEL + col;
                }
                float2 v = make_float2(acc[im][jn][half * 2 + 0] + b0,
                                       acc[im][jn][half * 2 + 1] + b1);
                *(float2*)(C + idx) = v;
            }
        }
    }
}

__global__ __launch_bounds__(256) void k_mma_qkv(const float* __restrict__ bq,
                                                 const float* __restrict__ bk,
                                                 const float* __restrict__ bv) {
    int z = blockIdx.z;
    const __nv_bfloat16* Ah = g_actH + (size_t)z * DMODEL * DMODEL;
    const __nv_bfloat16* Al = g_actL + (size_t)z * DMODEL * DMODEL;
    const __nv_bfloat16* Bh = g_WtH + (size_t)z * DMODEL * DMODEL;
    const __nv_bfloat16* Bl = g_WtL + (size_t)z * DMODEL * DMODEL;
    const float* bias = (z == 0) ? bq : (z == 1) ? bk : bv;
    float* C = (z == 0) ? g_Qp : (z == 1) ? g_Kp : g_Vp;
    mma_body<0>(Ah, Al, Bh, Bl, bias, C);
}

__global__ __launch_bounds__(256) void k_mma_out(const float* __restrict__ bo,
                                                 float* __restrict__ out) {
    mma_body<1>(g_attH, g_attL,
                g_WtH + (size_t)3 * DMODEL * DMODEL, g_WtL + (size_t)3 * DMODEL * DMODEL,
                bo, out);
}

// ---------------- fused attention (flash-style, fp32 SIMT) ----------------
__global__ __launch_bounds__(256) void k_attn() {
    __shared__ float Qs[64][64];
    __shared__ float KP[64][64];
    __shared__ float Vs[64][64];
    int b = blockIdx.z, h = blockIdx.y, q0 = blockIdx.x * 64;
    int t = threadIdx.x, tx = t & 15, ty = t >> 4;
    const float* Qg = g_Qp + (size_t)(b * NH + h) * SEQ * HDIM;
    const float* Kg = g_Kp + (size_t)(b * NH + h) * SEQ * HDIM;
    const float* Vg = g_Vp + (size_t)(b * NH + h) * SEQ * HDIM;
    const float* Bg = g_bias + ((size_t)(b * NH + h) * SEQ + q0) * SEQ;

#pragma unroll
    for (int u = 0; u < 4; u++) {
        int f = t + u * 256;
        int r = f & 63, cq = f >> 6;
        float4 v = *(const float4*)(Qg + (size_t)(q0 + r) * HDIM + cq * 4);
        Qs[cq * 4 + 0][r] = v.x; Qs[cq * 4 + 1][r] = v.y;
        Qs[cq * 4 + 2][r] = v.z; Qs[cq * 4 + 3][r] = v.w;
    }

    float m_[4], l_[4], acc[4][4];
#pragma unroll
    for (int i = 0; i < 4; i++) {
        m_[i] = -1e30f; l_[i] = 0.f;
#pragma unroll
        for (int j = 0; j < 4; j++) acc[i][j] = 0.f;
    }

    for (int k0 = 0; k0 < SEQ; k0 += 64) {
        __syncthreads();
#pragma unroll
        for (int u = 0; u < 4; u++) {
            int f = t + u * 256;
            int r = f & 63, cq = f >> 6;
            float4 kv = *(const float4*)(Kg + (size_t)(k0 + r) * HDIM + cq * 4);
            KP[cq * 4 + 0][r] = kv.x; KP[cq * 4 + 1][r] = kv.y;
            KP[cq * 4 + 2][r] = kv.z; KP[cq * 4 + 3][r] = kv.w;
            int rv = f >> 4, cv = (f & 15) * 4;
            float4 vv = *(const float4*)(Vg + (size_t)(k0 + rv) * HDIM + cv);
            *(float4*)&Vs[rv][cv] = vv;
        }
        __syncthreads();

        float s[4][4];
#pragma unroll
        for (int i = 0; i < 4; i++)
#pragma unroll
            for (int j = 0; j < 4; j++) s[i][j] = 0.f;
#pragma unroll 8
        for (int d = 0; d < 64; d++) {
            float4 qf = *(float4*)&Qs[d][ty * 4];
            float4 kf = *(float4*)&KP[d][tx * 4];
            float qa[4] = {qf.x, qf.y, qf.z, qf.w};
            float ka[4] = {kf.x, kf.y, kf.z, kf.w};
#pragma unroll
            for (int i = 0; i < 4; i++)
#pragma unroll
                for (int j = 0; j < 4; j++) s[i][j] += qa[i] * ka[j];
        }

#pragma unroll
        for (int ii = 0; ii < 4; ii++) {
            float4 bf = *(const float4*)(Bg + (size_t)(ty * 4 + ii) * SEQ + k0 + tx * 4);
            s[ii][0] = s[ii][0] * 0.125f + bf.x;
            s[ii][1] = s[ii][1] * 0.125f + bf.y;
            s[ii][2] = s[ii][2] * 0.125f + bf.z;
            s[ii][3] = s[ii][3] * 0.125f + bf.w;
            float mx = fmaxf(fmaxf(s[ii][0], s[ii][1]), fmaxf(s[ii][2], s[ii][3]));
#pragma unroll
            for (int o = 1; o < 16; o <<= 1) mx = fmaxf(mx, __shfl_xor_sync(0xffffffffu, mx, o));
            float mn = fmaxf(m_[ii], mx);
            float corr = __expf(m_[ii] - mn);
            float rs = 0.f;
#pragma unroll
            for (int j = 0; j < 4; j++) {
                float p = __expf(s[ii][j] - mn);
                s[ii][j] = p; rs += p;
            }
#pragma unroll
            for (int o = 1; o < 16; o <<= 1) rs += __shfl_xor_sync(0xffffffffu, rs, o);
            l_[ii] = l_[ii] * corr + rs;
            m_[ii] = mn;
#pragma unroll
            for (int j = 0; j < 4; j++) acc[ii][j] *= corr;
        }

        __syncthreads();
#pragma unroll
        for (int ii = 0; ii < 4; ii++)
            *(float4*)&KP[ty * 4 + ii][tx * 4] =
                make_float4(s[ii][0], s[ii][1], s[ii][2], s[ii][3]);
        __syncthreads();

#pragma unroll 8
        for (int k = 0; k < 64; k++) {
            float4 vf = *(float4*)&Vs[k][tx * 4];
            float va[4] = {vf.x, vf.y, vf.z, vf.w};
#pragma unroll
            for (int ii = 0; ii < 4; ii++) {
                float p = KP[ty * 4 + ii][k];
                acc[ii][0] += p * va[0]; acc[ii][1] += p * va[1];
                acc[ii][2] += p * va[2]; acc[ii][3] += p * va[3];
            }
        }
    }

#pragma unroll
    for (int ii = 0; ii < 4; ii++) {
        float rl = 1.f / l_[ii];
        int q = q0 + ty * 4 + ii;
        float4 o = make_float4(acc[ii][0] * rl, acc[ii][1] * rl,
                               acc[ii][2] * rl, acc[ii][3] * rl);
        *(float4*)(g_att + ((size_t)(b * SEQ + q) * NH + h) * HDIM + tx * 4) = o;
    }
}

// ---------------- launch ----------------
extern "C" void kernel_launch(void* const* d_in, const int* in_sizes, int n_in,
                              void* d_out, int out_size) {
    (void)in_sizes; (void)n_in; (void)out_size;
    const float* query = (const float*)d_in[0];
    const float* key   = (const float*)d_in[1];
    const float* value = (const float*)d_in[2];
    const float* qx    = (const float*)d_in[3];
    const float* qy    = (const float*)d_in[4];
    const float* kx    = (const float*)d_in[5];
    const float* ky    = (const float*)d_in[6];
    const float* Wq    = (const float*)d_in[7];
    const float* bq    = (const float*)d_in[8];
    const float* Wk    = (const float*)d_in[9];
    const float* bk    = (const float*)d_in[10];
    const float* Wv    = (const float*)d_in[11];
    const float* bv    = (const float*)d_in[12];
    const float* Wo    = (const float*)d_in[13];
    const float* bo    = (const float*)d_in[14];
    const float* xt    = (const float*)d_in[15];
    const float* yt    = (const float*)d_in[16];
    const float* Wb    = (const float*)d_in[17];
    const float* bb    = (const float*)d_in[18];
    float* out = (float*)d_out;

    k_project<<<(2 * NEMB * NH + 255) / 256, 256>>>(xt, yt, Wb);
    k_bias<<<dim3(SEQ / 16, SEQ / 16, NB), 256>>>(qx, qy, kx, ky, bb);
    k_convA<<<dim3(DMODEL * DMODEL / 4 / 256, 1, 3), 256>>>(query, key, value);
    k_convW<<<dim3(32, 32, 4), dim3(32, 8)>>>(Wq, Wk, Wv, Wo);
    k_mma_qkv<<<dim3(8, 8, 3), 256>>>(bq, bk, bv);
    k_attn<<<dim3(SEQ / 64, NH, NB), 256>>>();
    k_convAtt<<<DMODEL * DMODEL / 4 / 256, 256>>>();
    k_mma_out<<<dim3(8, 8), 256>>>(bo, out);
}